// round 3
// baseline (speedup 1.0000x reference)
#include <cuda_runtime.h>

// Problem constants
constexpr int kS = 2048;   // seq len
constexpr int kB = 64;     // batch
constexpr int kE = 512;    // embed
constexpr int kH = 256;    // hidden
constexpr int kG = 1024;   // 4*H

// Scratch for input projections: [2 dirs][S][B][4H] fp32 = 1.07 GB
__device__ float g_gx[2u * 2048u * 64u * 1024u];

// ---------------------------------------------------------------------------
// Helpers
// ---------------------------------------------------------------------------
__device__ __forceinline__ unsigned f2tf(float x) {
    unsigned r;
    asm("cvt.rna.tf32.f32 %0, %1;" : "=r"(r) : "f"(x));
    return r;
}

__device__ __forceinline__ void mma_tf32(float* c, const unsigned* a, const unsigned* b) {
    asm volatile(
        "mma.sync.aligned.m16n8k8.row.col.f32.tf32.tf32.f32 "
        "{%0,%1,%2,%3},{%4,%5,%6,%7},{%8,%9},{%0,%1,%2,%3};"
        : "+f"(c[0]), "+f"(c[1]), "+f"(c[2]), "+f"(c[3])
        : "r"(a[0]), "r"(a[1]), "r"(a[2]), "r"(a[3]), "r"(b[0]), "r"(b[1]));
}

__device__ __forceinline__ float sigf(float x) { return 1.f / (1.f + __expf(-x)); }
__device__ __forceinline__ float tanhf_(float x) { return 1.f - 2.f / (__expf(2.f * x) + 1.f); }

// ---------------------------------------------------------------------------
// Kernel 1: input projection GEMM (tf32 mma.sync), per direction
//   gx[d][s][b][j] = sum_e X[b][s][e] * W_ih[d][j][e] + (b_ih[d][j]+b_hh[d][j])
// Tile: 64(M=batch at fixed s) x 64(N) x 16(K); 128 threads, 2x2 warps, each
// warp 32x32 via m16n8k8.
// ---------------------------------------------------------------------------
__global__ void __launch_bounds__(128) gemm_in(
    const float* __restrict__ X,
    const float* __restrict__ Wf, const float* __restrict__ bif, const float* __restrict__ bhf,
    const float* __restrict__ Wb, const float* __restrict__ bib, const float* __restrict__ bhb)
{
    // padded stride 20 floats -> conflict-free fragment loads
    __shared__ unsigned As[64 * 20];
    __shared__ unsigned Bs[64 * 20];

    const int ntile = blockIdx.x;       // 0..15
    const int s     = blockIdx.y;       // 0..2047
    const int d     = blockIdx.z;       // 0..1
    const float* W  = d == 0 ? Wf : Wb;
    const float* bi = d == 0 ? bif : bib;
    const float* bh = d == 0 ? bhf : bhb;
    const int n0 = ntile * 64;

    const int tid  = threadIdx.x;
    const int lane = tid & 31;
    const int warp = tid >> 5;
    const int g  = lane >> 2;   // groupID
    const int t4 = lane & 3;    // thread-in-group
    const int wm = (warp >> 1) * 32;
    const int wn = (warp & 1) * 32;

    float acc[2][4][4];
#pragma unroll
    for (int mi = 0; mi < 2; mi++)
#pragma unroll
        for (int ni = 0; ni < 4; ni++)
#pragma unroll
            for (int q = 0; q < 4; q++) acc[mi][ni][q] = 0.f;

    const int lr = tid >> 2;         // 0..31
    const int lc = (tid & 3) * 4;    // 0,4,8,12

    for (int k0 = 0; k0 < kE; k0 += 16) {
        __syncthreads();
        // Stage A (X rows = batch, fixed s) and B (W rows) into SMEM as tf32
#pragma unroll
        for (int rr = 0; rr < 2; rr++) {
            const int row = lr + rr * 32;
            float4 va = *(const float4*)(X + ((size_t)row * kS + s) * kE + k0 + lc);
            unsigned* da = &As[row * 20 + lc];
            da[0] = f2tf(va.x); da[1] = f2tf(va.y); da[2] = f2tf(va.z); da[3] = f2tf(va.w);
            float4 vb = *(const float4*)(W + (size_t)(n0 + row) * kE + k0 + lc);
            unsigned* db = &Bs[row * 20 + lc];
            db[0] = f2tf(vb.x); db[1] = f2tf(vb.y); db[2] = f2tf(vb.z); db[3] = f2tf(vb.w);
        }
        __syncthreads();

#pragma unroll
        for (int kk = 0; kk < 2; kk++) {
            const int kb = kk * 8;
            unsigned a[2][4], b[4][2];
#pragma unroll
            for (int mi = 0; mi < 2; mi++) {
                const int ar = wm + mi * 16;
                a[mi][0] = As[(ar + g) * 20 + kb + t4];
                a[mi][1] = As[(ar + g + 8) * 20 + kb + t4];
                a[mi][2] = As[(ar + g) * 20 + kb + t4 + 4];
                a[mi][3] = As[(ar + g + 8) * 20 + kb + t4 + 4];
            }
#pragma unroll
            for (int ni = 0; ni < 4; ni++) {
                const int bc = wn + ni * 8;
                b[ni][0] = Bs[(bc + g) * 20 + kb + t4];
                b[ni][1] = Bs[(bc + g) * 20 + kb + t4 + 4];
            }
#pragma unroll
            for (int mi = 0; mi < 2; mi++)
#pragma unroll
                for (int ni = 0; ni < 4; ni++)
                    mma_tf32(acc[mi][ni], a[mi], b[ni]);
        }
    }

    // Epilogue: add bias, store to g_gx
    const size_t rbase = ((size_t)d * kS + s) * kB;
#pragma unroll
    for (int ni = 0; ni < 4; ni++) {
        const int col = n0 + wn + ni * 8 + t4 * 2;
        const float bs0 = bi[col] + bh[col];
        const float bs1 = bi[col + 1] + bh[col + 1];
#pragma unroll
        for (int mi = 0; mi < 2; mi++) {
            const int r0 = wm + mi * 16 + g;
            float2 v;
            v.x = acc[mi][ni][0] + bs0; v.y = acc[mi][ni][1] + bs1;
            *(float2*)&g_gx[(rbase + r0) * kG + col] = v;
            v.x = acc[mi][ni][2] + bs0; v.y = acc[mi][ni][3] + bs1;
            *(float2*)&g_gx[(rbase + r0 + 8) * kG + col] = v;
        }
    }
}

// ---------------------------------------------------------------------------
// Kernel 2: recurrence. 16 clusters of 8 CTAs (128 CTAs total, one wave).
// Cluster = (dir, batch-group of 8). CTA rank c owns hidden units
// [c*32, c*32+32) => 128 rows of w_hh (4 gates x 32 units), resident in SMEM.
// Per step: partial dots (K split 8-ways across lanes), shfl-reduce, gates,
// broadcast h-slice to peers via DSMEM, one barrier.cluster.
// ---------------------------------------------------------------------------
constexpr int WS_STRIDE = 260;                   // padded row stride (floats)
constexpr int SM_H  = 128 * WS_STRIDE;           // float offset of h buffers
constexpr int SM_G  = SM_H + 2 * 8 * kH;         // float offset of gpre
constexpr int SM_FLOATS = SM_G + 8 * 128;        // 38400 floats
constexpr int SM_BYTES  = SM_FLOATS * 4;         // 153600 B

__global__ void __launch_bounds__(256, 1) lstm_rec(
    const float* __restrict__ whf, const float* __restrict__ whb,
    const float* __restrict__ h0f, const float* __restrict__ c0f,
    const float* __restrict__ h0b, const float* __restrict__ c0b,
    float* __restrict__ out)
{
    extern __shared__ float sm[];
    float* ws = sm;               // [128][260]
    float* hb = sm + SM_H;        // [2][8][256]
    float* gp = sm + SM_G;        // [8][128]

    unsigned rank;
    asm("mov.u32 %0, %%cluster_ctarank;" : "=r"(rank));
    unsigned smbase;
    asm("{ .reg .u64 t; cvta.to.shared.u64 t, %1; cvt.u32.u64 %0, t; }"
        : "=r"(smbase) : "l"(sm));

    const int cid = blockIdx.x >> 3;   // cluster 0..15
    const int dir = cid >> 3;          // 0 fwd, 1 bwd
    const int bg  = cid & 7;
    const int gb0 = bg * 8;
    const int tid = threadIdx.x;

    const float* whh = dir == 0 ? whf : whb;
    const float* h0  = dir == 0 ? h0f : h0b;
    const float* c0  = dir == 0 ? c0f : c0b;

    // Load w_hh slice: local row r -> global row (r>>5)*256 + rank*32 + (r&31)
    for (int idx = tid; idx < 128 * 64; idx += 256) {
        const int r = idx >> 6, k4 = (idx & 63) * 4;
        const int grow = ((r >> 5) << 8) + (int)rank * 32 + (r & 31);
        float4 v = *(const float4*)(whh + (size_t)grow * kH + k4);
        *(float4*)(ws + r * WS_STRIDE + k4) = v;
    }
    // Load h0 (full vectors for our 8 batches) into buffer 0
    for (int idx = tid; idx < 8 * 64; idx += 256) {
        const int b = idx >> 6, k4 = (idx & 63) * 4;
        float4 v = *(const float4*)(h0 + (size_t)(gb0 + b) * kH + k4);
        *(float4*)(hb + b * kH + k4) = v;
    }

    // Per-thread persistent cell state (update mapping: b=tid/32, u=tid%32)
    const int ub = tid >> 5;
    const int uu = tid & 31;
    float cst = c0[(size_t)(gb0 + ub) * kH + (int)rank * 32 + uu];

    // K-loop mapping: rg = tid>>3 owns rows [4rg,4rg+4), ks = tid&7 owns K-slice
    const int rg = tid >> 3;
    const int ks = tid & 7;
    const int kbase = ks * 32;

    __syncthreads();
    // all CTAs fill only their own h buffer from global -> cluster barrier to
    // align everyone before the loop
    asm volatile("barrier.cluster.arrive.aligned;" ::: "memory");
    asm volatile("barrier.cluster.wait.aligned;" ::: "memory");

    int p = 0;
    for (int step = 0; step < kS; step++) {
        const int t = (dir == 0) ? step : (kS - 1 - step);

        // Prefetch gx for the update phase (independent of h -> hides DRAM)
        const size_t gxb = (((size_t)dir * kS + t) * kB + gb0 + ub) * kG
                           + (size_t)rank * 32 + uu;
        const float gx0 = g_gx[gxb];
        const float gx1 = g_gx[gxb + 256];
        const float gx2 = g_gx[gxb + 512];
        const float gx3 = g_gx[gxb + 768];

        // Partial dot products over our K-slice
        float acc[4][8];
#pragma unroll
        for (int i = 0; i < 4; i++)
#pragma unroll
            for (int b = 0; b < 8; b++) acc[i][b] = 0.f;

        const float* hcur = hb + p * 8 * kH;
#pragma unroll
        for (int kc = 0; kc < 8; kc++) {
            const int k = kbase + kc * 4;
            const float4 w0 = *(const float4*)(ws + (rg * 4 + 0) * WS_STRIDE + k);
            const float4 w1 = *(const float4*)(ws + (rg * 4 + 1) * WS_STRIDE + k);
            const float4 w2 = *(const float4*)(ws + (rg * 4 + 2) * WS_STRIDE + k);
            const float4 w3 = *(const float4*)(ws + (rg * 4 + 3) * WS_STRIDE + k);
#pragma unroll
            for (int b = 0; b < 8; b++) {
                const float4 h4 = *(const float4*)(hcur + b * kH + k);
                acc[0][b] = fmaf(w0.x, h4.x, fmaf(w0.y, h4.y, fmaf(w0.z, h4.z, fmaf(w0.w, h4.w, acc[0][b]))));
                acc[1][b] = fmaf(w1.x, h4.x, fmaf(w1.y, h4.y, fmaf(w1.z, h4.z, fmaf(w1.w, h4.w, acc[1][b]))));
                acc[2][b] = fmaf(w2.x, h4.x, fmaf(w2.y, h4.y, fmaf(w2.z, h4.z, fmaf(w2.w, h4.w, acc[2][b]))));
                acc[3][b] = fmaf(w3.x, h4.x, fmaf(w3.y, h4.y, fmaf(w3.z, h4.z, fmaf(w3.w, h4.w, acc[3][b]))));
            }
        }

        // Reduce the 8 K-slices (consecutive lanes within an octet)
#pragma unroll
        for (int i = 0; i < 4; i++)
#pragma unroll
            for (int b = 0; b < 8; b++) {
                float v = acc[i][b];
                v += __shfl_xor_sync(0xffffffffu, v, 1);
                v += __shfl_xor_sync(0xffffffffu, v, 2);
                v += __shfl_xor_sync(0xffffffffu, v, 4);
                acc[i][b] = v;
            }
        // Lane ks publishes batch==ks
#pragma unroll
        for (int i = 0; i < 4; i++) gp[ks * 128 + rg * 4 + i] = acc[i][ks];
        __syncthreads();

        // Gate math for (ub, uu)
        const float gi = gp[ub * 128 + uu]        + gx0;  // i
        const float gf = gp[ub * 128 + 32 + uu]   + gx1;  // f
        const float gg = gp[ub * 128 + 64 + uu]   + gx2;  // g
        const float go = gp[ub * 128 + 96 + uu]   + gx3;  // o
        cst = sigf(gf) * cst + sigf(gi) * tanhf_(gg);
        const float hnew = sigf(go) * tanhf_(cst);

        float* hnext = hb + (p ^ 1) * 8 * kH;
        hnext[ub * kH + (int)rank * 32 + uu] = hnew;
        out[(((size_t)(gb0 + ub)) * kS + t) * 512 + dir * kH + (int)rank * 32 + uu] = hnew;
        __syncthreads();

        // Broadcast our 8x32 h-slice to the 7 peer CTAs (float4 DSMEM stores)
        if (tid < 64) {
            const int b = tid >> 3, f4 = tid & 7;
            const float4 v = *(const float4*)(hnext + b * kH + (int)rank * 32 + f4 * 4);
            const unsigned loff = smbase +
                (unsigned)(SM_H + ((p ^ 1) * 8 + b) * kH + (int)rank * 32 + f4 * 4) * 4u;
#pragma unroll
            for (int pr = 0; pr < 8; pr++) {
                if (pr == (int)rank) continue;
                unsigned raddr;
                asm("mapa.shared::cluster.u32 %0, %1, %2;" : "=r"(raddr) : "r"(loff), "r"(pr));
                asm volatile("st.shared::cluster.v4.f32 [%0], {%1,%2,%3,%4};"
                             :: "r"(raddr), "f"(v.x), "f"(v.y), "f"(v.z), "f"(v.w));
            }
        }

        asm volatile("barrier.cluster.arrive.aligned;" ::: "memory");
        asm volatile("barrier.cluster.wait.aligned;" ::: "memory");
        p ^= 1;
    }
}

// ---------------------------------------------------------------------------
// Launch
// ---------------------------------------------------------------------------
extern "C" void kernel_launch(void* const* d_in, const int* in_sizes, int n_in,
                              void* d_out, int out_size)
{
    const float* X   = (const float*)d_in[0];
    const float* Wf  = (const float*)d_in[1];
    const float* Whf = (const float*)d_in[2];
    const float* bif = (const float*)d_in[3];
    const float* bhf = (const float*)d_in[4];
    const float* Wb  = (const float*)d_in[5];
    const float* Whb = (const float*)d_in[6];
    const float* bib = (const float*)d_in[7];
    const float* bhb = (const float*)d_in[8];
    const float* h0f = (const float*)d_in[9];
    const float* c0f = (const float*)d_in[10];
    const float* h0b = (const float*)d_in[11];
    const float* c0b = (const float*)d_in[12];
    float* out = (float*)d_out;

    cudaFuncSetAttribute(lstm_rec, cudaFuncAttributeMaxDynamicSharedMemorySize, SM_BYTES);

    dim3 g1(16, 2048, 2);
    gemm_in<<<g1, 128>>>(X, Wf, bif, bhf, Wb, bib, bhb);

    cudaLaunchConfig_t cfg = {};
    cfg.gridDim = dim3(128, 1, 1);
    cfg.blockDim = dim3(256, 1, 1);
    cfg.dynamicSmemBytes = SM_BYTES;
    cfg.stream = 0;
    cudaLaunchAttribute attr[1];
    attr[0].id = cudaLaunchAttributeClusterDimension;
    attr[0].val.clusterDim.x = 8;
    attr[0].val.clusterDim.y = 1;
    attr[0].val.clusterDim.z = 1;
    cfg.attrs = attr;
    cfg.numAttrs = 1;
    cudaLaunchKernelEx(&cfg, lstm_rec, Whf, Whb, h0f, c0f, h0b, c0b, out);
}

// round 6
// speedup vs baseline: 3.1800x; 3.1800x over previous
#include <cuda_runtime.h>

// Problem constants
constexpr int kS = 2048;   // seq len
constexpr int kB = 64;     // batch
constexpr int kE = 512;    // embed
constexpr int kH = 256;    // hidden
constexpr int kG = 1024;   // 4*H

// Scratch for input projections: [2 dirs][S][B][4H] fp32 = 1.07 GB
__device__ float g_gx[2u * 2048u * 64u * 1024u];

// ---------------------------------------------------------------------------
// Helpers
// ---------------------------------------------------------------------------
__device__ __forceinline__ unsigned f2tf(float x) {
    unsigned r;
    asm("cvt.rna.tf32.f32 %0, %1;" : "=r"(r) : "f"(x));
    return r;
}

__device__ __forceinline__ void mma_tf32(float* c, const unsigned* a, const unsigned* b) {
    asm volatile(
        "mma.sync.aligned.m16n8k8.row.col.f32.tf32.tf32.f32 "
        "{%0,%1,%2,%3},{%4,%5,%6,%7},{%8,%9},{%0,%1,%2,%3};"
        : "+f"(c[0]), "+f"(c[1]), "+f"(c[2]), "+f"(c[3])
        : "r"(a[0]), "r"(a[1]), "r"(a[2]), "r"(a[3]), "r"(b[0]), "r"(b[1]));
}

__device__ __forceinline__ float sigf(float x) { return 1.f / (1.f + __expf(-x)); }
__device__ __forceinline__ float tanhf_(float x) { return 1.f - 2.f / (__expf(2.f * x) + 1.f); }

// ---------------------------------------------------------------------------
// Kernel 1: input projection GEMM (tf32 mma.sync), per direction (unchanged)
// ---------------------------------------------------------------------------
__global__ void __launch_bounds__(128) gemm_in(
    const float* __restrict__ X,
    const float* __restrict__ Wf, const float* __restrict__ bif, const float* __restrict__ bhf,
    const float* __restrict__ Wb, const float* __restrict__ bib, const float* __restrict__ bhb)
{
    __shared__ unsigned As[64 * 20];
    __shared__ unsigned Bs[64 * 20];

    const int ntile = blockIdx.x;       // 0..15
    const int s     = blockIdx.y;       // 0..2047
    const int d     = blockIdx.z;       // 0..1
    const float* W  = d == 0 ? Wf : Wb;
    const float* bi = d == 0 ? bif : bib;
    const float* bh = d == 0 ? bhf : bhb;
    const int n0 = ntile * 64;

    const int tid  = threadIdx.x;
    const int lane = tid & 31;
    const int warp = tid >> 5;
    const int g  = lane >> 2;
    const int t4 = lane & 3;
    const int wm = (warp >> 1) * 32;
    const int wn = (warp & 1) * 32;

    float acc[2][4][4];
#pragma unroll
    for (int mi = 0; mi < 2; mi++)
#pragma unroll
        for (int ni = 0; ni < 4; ni++)
#pragma unroll
            for (int q = 0; q < 4; q++) acc[mi][ni][q] = 0.f;

    const int lr = tid >> 2;
    const int lc = (tid & 3) * 4;

    for (int k0 = 0; k0 < kE; k0 += 16) {
        __syncthreads();
#pragma unroll
        for (int rr = 0; rr < 2; rr++) {
            const int row = lr + rr * 32;
            float4 va = *(const float4*)(X + ((size_t)row * kS + s) * kE + k0 + lc);
            unsigned* da = &As[row * 20 + lc];
            da[0] = f2tf(va.x); da[1] = f2tf(va.y); da[2] = f2tf(va.z); da[3] = f2tf(va.w);
            float4 vb = *(const float4*)(W + (size_t)(n0 + row) * kE + k0 + lc);
            unsigned* db = &Bs[row * 20 + lc];
            db[0] = f2tf(vb.x); db[1] = f2tf(vb.y); db[2] = f2tf(vb.z); db[3] = f2tf(vb.w);
        }
        __syncthreads();

#pragma unroll
        for (int kk = 0; kk < 2; kk++) {
            const int kb = kk * 8;
            unsigned a[2][4], b[4][2];
#pragma unroll
            for (int mi = 0; mi < 2; mi++) {
                const int ar = wm + mi * 16;
                a[mi][0] = As[(ar + g) * 20 + kb + t4];
                a[mi][1] = As[(ar + g + 8) * 20 + kb + t4];
                a[mi][2] = As[(ar + g) * 20 + kb + t4 + 4];
                a[mi][3] = As[(ar + g + 8) * 20 + kb + t4 + 4];
            }
#pragma unroll
            for (int ni = 0; ni < 4; ni++) {
                const int bc = wn + ni * 8;
                b[ni][0] = Bs[(bc + g) * 20 + kb + t4];
                b[ni][1] = Bs[(bc + g) * 20 + kb + t4 + 4];
            }
#pragma unroll
            for (int mi = 0; mi < 2; mi++)
#pragma unroll
                for (int ni = 0; ni < 4; ni++)
                    mma_tf32(acc[mi][ni], a[mi], b[ni]);
        }
    }

    const size_t rbase = ((size_t)d * kS + s) * kB;
#pragma unroll
    for (int ni = 0; ni < 4; ni++) {
        const int col = n0 + wn + ni * 8 + t4 * 2;
        const float bs0 = bi[col] + bh[col];
        const float bs1 = bi[col + 1] + bh[col + 1];
#pragma unroll
        for (int mi = 0; mi < 2; mi++) {
            const int r0 = wm + mi * 16 + g;
            float2 v;
            v.x = acc[mi][ni][0] + bs0; v.y = acc[mi][ni][1] + bs1;
            *(float2*)&g_gx[(rbase + r0) * kG + col] = v;
            v.x = acc[mi][ni][2] + bs0; v.y = acc[mi][ni][3] + bs1;
            *(float2*)&g_gx[(rbase + r0 + 8) * kG + col] = v;
        }
    }
}

// ---------------------------------------------------------------------------
// Kernel 2: recurrence. 16 clusters of 8 CTAs, 512 threads/CTA.
// CTA rank c owns hidden units [c*32, c*32+32) => 128 gate rows of w_hh,
// held ENTIRELY IN REGISTERS (64 regs/thread: 2 rows x 32-K-slice).
// Thread map: rp = tid>>3 (row pair, 0..63), ks = tid&7 (K slice of 32).
// K interleave: k = kc*32 + ks*4 -> conflict-free h LDS.128 (8 bank quads,
// 4-lane broadcast). Per step: FMA -> shfl reduce over ks -> gates ->
// DSMEM broadcast of own h slice -> barrier.cluster.
// ---------------------------------------------------------------------------
constexpr int GP_STRIDE = 132;   // padded so publish stores spread banks

__global__ void __launch_bounds__(512, 1) lstm_rec(
    const float* __restrict__ whf, const float* __restrict__ whb,
    const float* __restrict__ h0f, const float* __restrict__ c0f,
    const float* __restrict__ h0b, const float* __restrict__ c0b,
    float* __restrict__ out)
{
    __shared__ float hb[2][8][kH];          // double-buffered h, 8 batches
    __shared__ float gp[8][GP_STRIDE];      // gate pre-activations per batch

    unsigned rank;
    asm("mov.u32 %0, %%cluster_ctarank;" : "=r"(rank));
    unsigned hb_base;
    asm("{ .reg .u64 t; cvta.to.shared.u64 t, %1; cvt.u32.u64 %0, t; }"
        : "=r"(hb_base) : "l"(&hb[0][0][0]));

    const int cid = blockIdx.x >> 3;   // cluster 0..15
    const int dir = cid >> 3;          // 0 fwd, 1 bwd
    const int bg  = cid & 7;
    const int gb0 = bg * 8;
    const int tid = threadIdx.x;

    const float* whh = dir == 0 ? whf : whb;
    const float* h0  = dir == 0 ? h0f : h0b;
    const float* c0  = dir == 0 ? c0f : c0b;

    const int rp = tid >> 3;           // 0..63 : rows 2rp, 2rp+1
    const int ks = tid & 7;            // K slice

    // Local row r -> global w_hh row: gate = r>>5, unit = rank*32 + (r&31)
    const int r0 = rp * 2, r1 = r0 + 1;
    const int gr0 = ((r0 >> 5) << 8) + (int)rank * 32 + (r0 & 31);
    const int gr1 = ((r1 >> 5) << 8) + (int)rank * 32 + (r1 & 31);

    // Persistent weight registers: 2 rows x 8 float4 (k = kc*32 + ks*4)
    float4 w0[8], w1[8];
#pragma unroll
    for (int kc = 0; kc < 8; kc++) {
        const int k = kc * 32 + ks * 4;
        w0[kc] = *(const float4*)(whh + (size_t)gr0 * kH + k);
        w1[kc] = *(const float4*)(whh + (size_t)gr1 * kH + k);
    }

    // Load h0 into buffer 0
    for (int idx = tid; idx < 8 * 64; idx += 512) {
        const int b = idx >> 6, k4 = (idx & 63) * 4;
        *(float4*)&hb[0][b][k4] = *(const float4*)(h0 + (size_t)(gb0 + b) * kH + k4);
    }

    // Gate-phase mapping (tid < 256): b = tid>>5, u = tid&31
    const int ub = tid >> 5;
    const int uu = tid & 31;
    float cst = 0.f;
    if (tid < 256) cst = c0[(size_t)(gb0 + ub) * kH + (int)rank * 32 + uu];

    // Broadcast mapping (tid < 448): one float4 remote store each
    const int pr0 = tid >> 6;                       // 0..6
    const int pr  = pr0 + (pr0 >= (int)rank ? 1 : 0);
    const int bb  = (tid & 63) >> 3;
    const int bf4 = (tid & 7) * 4;

    __syncthreads();
    asm volatile("barrier.cluster.arrive.aligned;" ::: "memory");
    asm volatile("barrier.cluster.wait.aligned;" ::: "memory");

    int p = 0;
    for (int step = 0; step < kS; step++) {
        const int t = (dir == 0) ? step : (kS - 1 - step);

        // Prefetch gx (independent of h -> hides DRAM under FMA)
        float gx0 = 0.f, gx1 = 0.f, gx2 = 0.f, gx3 = 0.f;
        if (tid < 256) {
            const size_t gxb = (((size_t)dir * kS + t) * kB + gb0 + ub) * kG
                               + (size_t)rank * 32 + uu;
            gx0 = g_gx[gxb];
            gx1 = g_gx[gxb + 256];
            gx2 = g_gx[gxb + 512];
            gx3 = g_gx[gxb + 768];
        }

        // Partial dots: 2 rows x 8 batches over our 32-element K slice
        float a0[8], a1[8];
#pragma unroll
        for (int b = 0; b < 8; b++) { a0[b] = 0.f; a1[b] = 0.f; }

        const float* hcur = &hb[p][0][0];
#pragma unroll
        for (int kc = 0; kc < 8; kc++) {
            const int k = kc * 32 + ks * 4;
            const float4 wv0 = w0[kc];
            const float4 wv1 = w1[kc];
#pragma unroll
            for (int b = 0; b < 8; b++) {
                const float4 h4 = *(const float4*)(hcur + b * kH + k);
                a0[b] = fmaf(wv0.x, h4.x, fmaf(wv0.y, h4.y, fmaf(wv0.z, h4.z, fmaf(wv0.w, h4.w, a0[b]))));
                a1[b] = fmaf(wv1.x, h4.x, fmaf(wv1.y, h4.y, fmaf(wv1.z, h4.z, fmaf(wv1.w, h4.w, a1[b]))));
            }
        }

        // Reduce over the 8 K-slices (lane bits 0..2 == ks)
#pragma unroll
        for (int b = 0; b < 8; b++) {
            float v0 = a0[b], v1 = a1[b];
            v0 += __shfl_xor_sync(0xffffffffu, v0, 1);
            v1 += __shfl_xor_sync(0xffffffffu, v1, 1);
            v0 += __shfl_xor_sync(0xffffffffu, v0, 2);
            v1 += __shfl_xor_sync(0xffffffffu, v1, 2);
            v0 += __shfl_xor_sync(0xffffffffu, v0, 4);
            v1 += __shfl_xor_sync(0xffffffffu, v1, 4);
            a0[b] = v0; a1[b] = v1;
        }
        // Lane ks publishes batch==ks: rows 2rp, 2rp+1
        {
            float2 v; v.x = a0[ks]; v.y = a1[ks];
            *(float2*)&gp[ks][rp * 2] = v;
        }
        __syncthreads();

        float hnew = 0.f;
        if (tid < 256) {
            const float gi = gp[ub][uu]        + gx0;  // i
            const float gf = gp[ub][32 + uu]   + gx1;  // f
            const float gg = gp[ub][64 + uu]   + gx2;  // g
            const float go = gp[ub][96 + uu]   + gx3;  // o
            cst = sigf(gf) * cst + sigf(gi) * tanhf_(gg);
            hnew = sigf(go) * tanhf_(cst);
            hb[p ^ 1][ub][(int)rank * 32 + uu] = hnew;
            out[(((size_t)(gb0 + ub)) * kS + t) * 512 + dir * kH + (int)rank * 32 + uu] = hnew;
        }
        __syncthreads();

        // Broadcast our 8x32 h-slice to the 7 peer CTAs (1 float4/thread)
        if (tid < 448) {
            const float4 v = *(const float4*)&hb[p ^ 1][bb][(int)rank * 32 + bf4];
            const unsigned loff = hb_base +
                (unsigned)(((p ^ 1) * 8 + bb) * kH + (int)rank * 32 + bf4) * 4u;
            unsigned raddr;
            asm("mapa.shared::cluster.u32 %0, %1, %2;" : "=r"(raddr) : "r"(loff), "r"(pr));
            asm volatile("st.shared::cluster.v4.f32 [%0], {%1,%2,%3,%4};"
                         :: "r"(raddr), "f"(v.x), "f"(v.y), "f"(v.z), "f"(v.w));
        }

        asm volatile("barrier.cluster.arrive.aligned;" ::: "memory");
        asm volatile("barrier.cluster.wait.aligned;" ::: "memory");
        p ^= 1;
    }
}

// ---------------------------------------------------------------------------
// Launch
// ---------------------------------------------------------------------------
extern "C" void kernel_launch(void* const* d_in, const int* in_sizes, int n_in,
                              void* d_out, int out_size)
{
    const float* X   = (const float*)d_in[0];
    const float* Wf  = (const float*)d_in[1];
    const float* Whf = (const float*)d_in[2];
    const float* bif = (const float*)d_in[3];
    const float* bhf = (const float*)d_in[4];
    const float* Wb  = (const float*)d_in[5];
    const float* Whb = (const float*)d_in[6];
    const float* bib = (const float*)d_in[7];
    const float* bhb = (const float*)d_in[8];
    const float* h0f = (const float*)d_in[9];
    const float* c0f = (const float*)d_in[10];
    const float* h0b = (const float*)d_in[11];
    const float* c0b = (const float*)d_in[12];
    float* out = (float*)d_out;

    dim3 g1(16, 2048, 2);
    gemm_in<<<g1, 128>>>(X, Wf, bif, bhf, Wb, bib, bhb);

    cudaLaunchConfig_t cfg = {};
    cfg.gridDim = dim3(128, 1, 1);
    cfg.blockDim = dim3(512, 1, 1);
    cfg.dynamicSmemBytes = 0;
    cfg.stream = 0;
    cudaLaunchAttribute attr[1];
    attr[0].id = cudaLaunchAttributeClusterDimension;
    attr[0].val.clusterDim.x = 8;
    attr[0].val.clusterDim.y = 1;
    attr[0].val.clusterDim.z = 1;
    cfg.attrs = attr;
    cfg.numAttrs = 1;
    cudaLaunchKernelEx(&cfg, lstm_rec, Whf, Whb, h0f, c0f, h0b, c0b, out);
}